// round 16
// baseline (speedup 1.0000x reference)
#include <cuda_runtime.h>
#include <cstdint>

#define NUM_B 32
#define NUM_C 128
#define NSEG (NUM_B * NUM_C)

#define THREADS 256
#define GRID_BLOCKS 152            // 1 CTA/SM (128 KB bins), one wave
#define UNROLL 4

// Per-thread u32 bins: bits[0:24) = sum * 2^14, bits[24:32) = count.
#define P_CNT_SHIFT 24
#define P_SUM_MASK ((1u << P_CNT_SHIFT) - 1u)
#define P_SCALE 16384.0f
// Global u64 bins: bits[0:40) = sum * 2^14, bits[40:64) = count.
#define G_CNT_SHIFT 40
#define G_SUM_MASK ((1ULL << G_CNT_SHIFT) - 1ULL)
#define INV_SCALE (1.0f / 16384.0f)

#define SMEM_BYTES (THREADS * NUM_C * 4)   // 128 KB of per-thread bins

struct alignas(128) PadBin {
    unsigned long long v;
    unsigned long long pad[15];
};
__device__ PadBin g_bins[NSEG];   // zero-init; last block re-zeros each run
__device__ unsigned int g_done;

// Only used OUTSIDE the hot loop (rare paths): safe to carry a memory clobber.
__device__ __forceinline__ void red_u64(unsigned long long* p, unsigned long long v) {
    asm volatile("red.global.add.u64 [%0], %1;" :: "l"(p), "l"(v) : "memory");
}
__device__ __forceinline__ unsigned long long pack1(float sq) {
    return (1ULL << G_CNT_SHIFT) + (unsigned long long)(sq * P_SCALE + 0.5f);
}

// ---------------- block-local flush ----------------
__device__ void flush_bins(unsigned* bins, int b_prim, int tid, bool rezero) {
    __syncthreads();
    const int c = tid & (NUM_C - 1);
    const int h = tid >> 7;
    unsigned cnt = 0, sum = 0;
    const uint4* row = (const uint4*)&bins[c * THREADS + h * 128];
#pragma unroll 8
    for (int j = 0; j < 32; j++) {
        uint4 v = row[(j + tid) & 31];
        cnt += (v.x >> P_CNT_SHIFT) + (v.y >> P_CNT_SHIFT) +
               (v.z >> P_CNT_SHIFT) + (v.w >> P_CNT_SHIFT);
        sum += (v.x & P_SUM_MASK) + (v.y & P_SUM_MASK) +
               (v.z & P_SUM_MASK) + (v.w & P_SUM_MASK);
    }
    __syncthreads();
    bins[tid] = sum;
    bins[THREADS + tid] = cnt;
    __syncthreads();
    if (tid < NUM_C) {
        unsigned ts = sum + bins[tid + 128];
        unsigned tc = cnt + bins[THREADS + tid + 128];
        if (tc)
            red_u64(&g_bins[b_prim * NUM_C + tid].v,
                    ((unsigned long long)tc << G_CNT_SHIFT) | (unsigned long long)ts);
    }
    if (rezero) {
        __syncthreads();
        uint4* z = (uint4*)bins;
#pragma unroll
        for (int j = 0; j < 32; j++) z[tid * 32 + j] = make_uint4(0u, 0u, 0u, 0u);
    }
    __syncthreads();
}

// ---------------- hot accumulator: NO asm, NO branches, batched loads ----------
__device__ __forceinline__ void accum_range(
    unsigned* __restrict__ bins,
    const float4* __restrict__ r4, const float4* __restrict__ t4,
    const int4* __restrict__ c4, int lo4, int hi4, int tid) {
    int i = lo4 + tid;
    // Unrolled main: 12 LDG.128 batched up front, then 16 independent RMW chains.
    for (; i + (UNROLL - 1) * THREADS < hi4; i += UNROLL * THREADS) {
        float4 rb[UNROLL], tb[UNROLL];
        int4 cb[UNROLL];
#pragma unroll
        for (int j = 0; j < UNROLL; j++) {
            rb[j] = r4[i + j * THREADS];
            tb[j] = t4[i + j * THREADS];
            cb[j] = c4[i + j * THREADS];
        }
#pragma unroll
        for (int j = 0; j < UNROLL; j++) {
            float d0 = rb[j].x - tb[j].x, d1 = rb[j].y - tb[j].y;
            float d2 = rb[j].z - tb[j].z, d3 = rb[j].w - tb[j].w;
            bins[cb[j].x * THREADS + tid] +=
                (1u << P_CNT_SHIFT) + (unsigned)(d0 * d0 * P_SCALE + 0.5f);
            bins[cb[j].y * THREADS + tid] +=
                (1u << P_CNT_SHIFT) + (unsigned)(d1 * d1 * P_SCALE + 0.5f);
            bins[cb[j].z * THREADS + tid] +=
                (1u << P_CNT_SHIFT) + (unsigned)(d2 * d2 * P_SCALE + 0.5f);
            bins[cb[j].w * THREADS + tid] +=
                (1u << P_CNT_SHIFT) + (unsigned)(d3 * d3 * P_SCALE + 0.5f);
        }
    }
    // remainder
    for (; i < hi4; i += THREADS) {
        float4 r = r4[i], t = t4[i];
        int4 c = c4[i];
        float d0 = r.x - t.x, d1 = r.y - t.y, d2 = r.z - t.z, d3 = r.w - t.w;
        bins[c.x * THREADS + tid] +=
            (1u << P_CNT_SHIFT) + (unsigned)(d0 * d0 * P_SCALE + 0.5f);
        bins[c.y * THREADS + tid] +=
            (1u << P_CNT_SHIFT) + (unsigned)(d1 * d1 * P_SCALE + 0.5f);
        bins[c.z * THREADS + tid] +=
            (1u << P_CNT_SHIFT) + (unsigned)(d2 * d2 * P_SCALE + 0.5f);
        bins[c.w * THREADS + tid] +=
            (1u << P_CNT_SHIFT) + (unsigned)(d3 * d3 * P_SCALE + 0.5f);
    }
}

// ---------------- main kernel ----------------
__global__ void __launch_bounds__(THREADS)
fused_loss_kernel(const float* __restrict__ reco,
                  const float* __restrict__ target,
                  const int* __restrict__ clabel,
                  const int* __restrict__ bindex,
                  int n, int n4, int chunk4, int nblocks,
                  float* __restrict__ out) {
    extern __shared__ __align__(128) unsigned bins[];  // [NUM_C][THREADS]
    const int tid = threadIdx.x;
    const int start4 = blockIdx.x * chunk4;
    const int end4 = min(start4 + chunk4, n4);

    __shared__ int s_lo, s_hi;

    if (start4 < n4) {
        // zero private bins (128 KB)
        {
            uint4* z = (uint4*)bins;
#pragma unroll
            for (int j = 0; j < 32; j++) z[tid * 32 + j] = make_uint4(0u, 0u, 0u, 0u);
        }

        const bool last_chunk = (end4 == n4);
        const int E0 = start4 * 4;
        const int E1 = last_chunk ? (n - 1) : (end4 * 4 - 1);
        const int b0 = __ldg(&bindex[E0]);
        const int b1 = __ldg(&bindex[E1]);

        const float4* r4 = (const float4*)reco;
        const float4* t4 = (const float4*)target;
        const int4* c4 = (const int4*)clabel;

        if (b0 == b1) {
            __syncthreads();
            accum_range(bins, r4, t4, c4, start4, end4, tid);
            flush_bins(bins, b0, tid, false);
        } else {
            // Binary search: S = first element index with bindex == b1.
            if (tid == 0) { s_lo = E0; s_hi = E1; }
            __syncthreads();
            while (true) {
                int lo = s_lo, hi = s_hi;
                if (hi - lo <= 1) break;
                __syncthreads();
                long span = hi - lo;
                int pos = lo + (int)((span * (long)(tid + 1)) / (THREADS + 1));
                if (pos > lo && pos < hi) {
                    if (__ldg(&bindex[pos]) < b1) atomicMax(&s_lo, pos);
                    else                          atomicMin(&s_hi, pos);
                }
                __syncthreads();
            }
            const int S = s_hi;
            __syncthreads();

            const int SA = S >> 2;        // float4 index containing the split
            const int Sr = S & 3;
            const int bstart = SA + (Sr ? 1 : 0);

            // Range A: pure b0
            accum_range(bins, r4, t4, c4, start4, SA, tid);
            // Bridge float4 (split mid-vector): <=4 direct REDs by tid 0
            if (Sr && tid == 0) {
                float4 r = r4[SA], t = t4[SA];
                int4 c = c4[SA];
                float d0 = r.x - t.x, d1 = r.y - t.y, d2 = r.z - t.z, d3 = r.w - t.w;
                int e = SA * 4;
                red_u64(&g_bins[(e + 0 < S ? b0 : b1) * NUM_C + c.x].v, pack1(d0 * d0));
                red_u64(&g_bins[(e + 1 < S ? b0 : b1) * NUM_C + c.y].v, pack1(d1 * d1));
                red_u64(&g_bins[(e + 2 < S ? b0 : b1) * NUM_C + c.z].v, pack1(d2 * d2));
                red_u64(&g_bins[(e + 3 < S ? b0 : b1) * NUM_C + c.w].v, pack1(d3 * d3));
            }
            flush_bins(bins, b0, tid, true);
            // Range B: pure b1
            accum_range(bins, r4, t4, c4, bstart, end4, tid);
            flush_bins(bins, b1, tid, false);
        }

        // scalar tail (n % 4 != 0), last chunk only
        if (last_chunk) {
            for (int i = n4 * 4 + tid; i < n; i += THREADS) {
                float d = __ldg(&reco[i]) - __ldg(&target[i]);
                red_u64(&g_bins[__ldg(&bindex[i]) * NUM_C + __ldg(&clabel[i])].v,
                        pack1(d * d));
            }
        }
    }

    // ---- completion counter; last block finalizes ----
    __threadfence();
    __syncthreads();
    __shared__ unsigned int s_is_last;
    if (tid == 0) {
        unsigned int old = atomicAdd(&g_done, 1u);
        s_is_last = (old == (unsigned int)(nblocks - 1)) ? 1u : 0u;
    }
    __syncthreads();
    if (!s_is_last) return;
    __threadfence();

    __shared__ float s_bsum[NUM_B];
    __shared__ float s_bcnt[NUM_B];
    if (tid < NUM_B) {
        s_bsum[tid] = 0.0f;
        s_bcnt[tid] = 0.0f;
    }
    __syncthreads();

    for (int sg = tid; sg < NSEG; sg += THREADS) {
        unsigned long long v = __ldcg(&g_bins[sg].v);
        g_bins[sg].v = 0ULL;  // re-zero for next launch
        unsigned int cnt = (unsigned int)(v >> G_CNT_SHIFT);
        if (cnt) {
            float sum = (float)(v & G_SUM_MASK) * INV_SCALE;
            atomicAdd(&s_bsum[sg >> 7], sum / (float)cnt);
            atomicAdd(&s_bcnt[sg >> 7], 1.0f);
        }
    }
    __syncthreads();

    if (tid < 32) {
        float bl = 0.0f, bp = 0.0f;
        float c = s_bcnt[tid];
        if (c > 0.0f) {
            bl = s_bsum[tid] / c;
            bp = 1.0f;
        }
#pragma unroll
        for (int off = 16; off > 0; off >>= 1) {
            bl += __shfl_down_sync(0xFFFFFFFFu, bl, off);
            bp += __shfl_down_sync(0xFFFFFFFFu, bp, off);
        }
        if (tid == 0) {
            out[0] = bl / bp;
            g_done = 0u;  // reset for next launch
        }
    }
}

extern "C" void kernel_launch(void* const* d_in, const int* in_sizes, int n_in,
                              void* d_out, int out_size) {
    const float* reco = (const float*)d_in[0];
    const float* target = (const float*)d_in[1];
    const int* clabel = (const int*)d_in[2];
    const int* bindex = (const int*)d_in[3];
    float* out = (float*)d_out;

    const int n = in_sizes[0];
    const int n4 = n >> 2;
    const int chunk4 = (n4 + GRID_BLOCKS - 1) / GRID_BLOCKS;

    cudaFuncSetAttribute(fused_loss_kernel,
                         cudaFuncAttributeMaxDynamicSharedMemorySize, SMEM_BYTES);

    fused_loss_kernel<<<GRID_BLOCKS, THREADS, SMEM_BYTES>>>(
        reco, target, clabel, bindex, n, n4, chunk4, GRID_BLOCKS, out);
}

// round 17
// speedup vs baseline: 1.0559x; 1.0559x over previous
#include <cuda_runtime.h>
#include <cstdint>

#define NUM_B 32
#define NUM_C 128
#define NSEG (NUM_B * NUM_C)

#define THREADS 256
#define GRID_BLOCKS 152            // 1 CTA/SM (128 KB bins), one wave
#define UNROLL 4

// Per-thread u32 bins: bits[0:24) = sum * 2^14, bits[24:32) = count.
#define P_CNT_SHIFT 24
#define P_SUM_MASK ((1u << P_CNT_SHIFT) - 1u)
#define P_SCALE 16384.0f
// Global u64 bins: bits[0:40) = sum * 2^14, bits[40:64) = count.
#define G_CNT_SHIFT 40
#define G_SUM_MASK ((1ULL << G_CNT_SHIFT) - 1ULL)
#define INV_SCALE (1.0f / 16384.0f)

#define SMEM_BYTES (THREADS * NUM_C * 4)   // 128 KB of per-thread bins

struct alignas(128) PadBin {
    unsigned long long v;
    unsigned long long pad[15];
};
__device__ PadBin g_bins[NSEG];   // zero-init; last block re-zeros each run
__device__ unsigned int g_done;

// Only used OUTSIDE the hot loop (rare paths).
__device__ __forceinline__ void red_u64(unsigned long long* p, unsigned long long v) {
    asm volatile("red.global.add.u64 [%0], %1;" :: "l"(p), "l"(v) : "memory");
}
__device__ __forceinline__ unsigned long long pack1(float sq) {
    return (1ULL << G_CNT_SHIFT) + (unsigned long long)(sq * P_SCALE + 0.5f);
}

// ---- dedup-merged 4-way RMW: 4 batched LDS then 4 STS, one latency window ----
// Duplicate clusters within the float4 are merged in registers, making the
// surviving addresses provably distinct, so loads may legally precede stores.
__device__ __forceinline__ void rmw4(unsigned* __restrict__ bins, int tid, int4 c,
                                     unsigned p0, unsigned p1,
                                     unsigned p2, unsigned p3) {
    const bool a1 = (c.y != c.x);
    const bool a2 = (c.z != c.x) && (c.z != c.y);
    const bool a3 = (c.w != c.x) && (c.w != c.y) && (c.w != c.z);
    if (!a1) p0 += p1;
    if (c.z == c.x) p0 += p2;
    else if (c.z == c.y) p1 += p2;
    if (c.w == c.x) p0 += p3;
    else if (c.w == c.y) p1 += p3;
    else if (c.w == c.z) p2 += p3;

    unsigned* A0 = &bins[c.x * THREADS + tid];
    unsigned* A1 = &bins[c.y * THREADS + tid];
    unsigned* A2 = &bins[c.z * THREADS + tid];
    unsigned* A3 = &bins[c.w * THREADS + tid];

    // batched loads (distinct addresses among active slots)
    unsigned o0 = *A0;
    unsigned o1 = a1 ? *A1 : 0u;
    unsigned o2 = a2 ? *A2 : 0u;
    unsigned o3 = a3 ? *A3 : 0u;
    // batched stores
    *A0 = o0 + p0;
    if (a1) *A1 = o1 + p1;
    if (a2) *A2 = o2 + p2;
    if (a3) *A3 = o3 + p3;
}

__device__ __forceinline__ unsigned packp(float q) {
    return (1u << P_CNT_SHIFT) + (unsigned)(q * P_SCALE + 0.5f);
}

// ---------------- block-local flush ----------------
__device__ void flush_bins(unsigned* bins, int b_prim, int tid, bool rezero) {
    __syncthreads();
    const int c = tid & (NUM_C - 1);
    const int h = tid >> 7;
    unsigned cnt = 0, sum = 0;
    const uint4* row = (const uint4*)&bins[c * THREADS + h * 128];
#pragma unroll 8
    for (int j = 0; j < 32; j++) {
        uint4 v = row[(j + tid) & 31];
        cnt += (v.x >> P_CNT_SHIFT) + (v.y >> P_CNT_SHIFT) +
               (v.z >> P_CNT_SHIFT) + (v.w >> P_CNT_SHIFT);
        sum += (v.x & P_SUM_MASK) + (v.y & P_SUM_MASK) +
               (v.z & P_SUM_MASK) + (v.w & P_SUM_MASK);
    }
    __syncthreads();
    bins[tid] = sum;
    bins[THREADS + tid] = cnt;
    __syncthreads();
    if (tid < NUM_C) {
        unsigned ts = sum + bins[tid + 128];
        unsigned tc = cnt + bins[THREADS + tid + 128];
        if (tc)
            red_u64(&g_bins[b_prim * NUM_C + tid].v,
                    ((unsigned long long)tc << G_CNT_SHIFT) | (unsigned long long)ts);
    }
    if (rezero) {
        __syncthreads();
        uint4* z = (uint4*)bins;
#pragma unroll
        for (int j = 0; j < 32; j++) z[tid * 32 + j] = make_uint4(0u, 0u, 0u, 0u);
    }
    __syncthreads();
}

// ---------------- hot accumulator ----------------
__device__ __forceinline__ void accum_range(
    unsigned* __restrict__ bins,
    const float4* __restrict__ r4, const float4* __restrict__ t4,
    const int4* __restrict__ c4, int lo4, int hi4, int tid) {
    int i = lo4 + tid;
    for (; i + (UNROLL - 1) * THREADS < hi4; i += UNROLL * THREADS) {
        float4 rb[UNROLL], tb[UNROLL];
        int4 cb[UNROLL];
#pragma unroll
        for (int j = 0; j < UNROLL; j++) {
            rb[j] = r4[i + j * THREADS];
            tb[j] = t4[i + j * THREADS];
            cb[j] = c4[i + j * THREADS];
        }
#pragma unroll
        for (int j = 0; j < UNROLL; j++) {
            float d0 = rb[j].x - tb[j].x, d1 = rb[j].y - tb[j].y;
            float d2 = rb[j].z - tb[j].z, d3 = rb[j].w - tb[j].w;
            rmw4(bins, tid, cb[j],
                 packp(d0 * d0), packp(d1 * d1), packp(d2 * d2), packp(d3 * d3));
        }
    }
    for (; i < hi4; i += THREADS) {
        float4 r = r4[i], t = t4[i];
        int4 c = c4[i];
        float d0 = r.x - t.x, d1 = r.y - t.y, d2 = r.z - t.z, d3 = r.w - t.w;
        rmw4(bins, tid, c,
             packp(d0 * d0), packp(d1 * d1), packp(d2 * d2), packp(d3 * d3));
    }
}

// ---------------- main kernel ----------------
__global__ void __launch_bounds__(THREADS)
fused_loss_kernel(const float* __restrict__ reco,
                  const float* __restrict__ target,
                  const int* __restrict__ clabel,
                  const int* __restrict__ bindex,
                  int n, int n4, int chunk4, int nblocks,
                  float* __restrict__ out) {
    extern __shared__ __align__(128) unsigned bins[];  // [NUM_C][THREADS]
    const int tid = threadIdx.x;
    const int start4 = blockIdx.x * chunk4;
    const int end4 = min(start4 + chunk4, n4);

    __shared__ int s_lo, s_hi;

    if (start4 < n4) {
        {
            uint4* z = (uint4*)bins;
#pragma unroll
            for (int j = 0; j < 32; j++) z[tid * 32 + j] = make_uint4(0u, 0u, 0u, 0u);
        }

        const bool last_chunk = (end4 == n4);
        const int E0 = start4 * 4;
        const int E1 = last_chunk ? (n - 1) : (end4 * 4 - 1);
        const int b0 = __ldg(&bindex[E0]);
        const int b1 = __ldg(&bindex[E1]);

        const float4* r4 = (const float4*)reco;
        const float4* t4 = (const float4*)target;
        const int4* c4 = (const int4*)clabel;

        if (b0 == b1) {
            __syncthreads();
            accum_range(bins, r4, t4, c4, start4, end4, tid);
            flush_bins(bins, b0, tid, false);
        } else {
            // Binary search: S = first element index with bindex == b1.
            if (tid == 0) { s_lo = E0; s_hi = E1; }
            __syncthreads();
            while (true) {
                int lo = s_lo, hi = s_hi;
                if (hi - lo <= 1) break;
                __syncthreads();
                long span = hi - lo;
                int pos = lo + (int)((span * (long)(tid + 1)) / (THREADS + 1));
                if (pos > lo && pos < hi) {
                    if (__ldg(&bindex[pos]) < b1) atomicMax(&s_lo, pos);
                    else                          atomicMin(&s_hi, pos);
                }
                __syncthreads();
            }
            const int S = s_hi;
            __syncthreads();

            const int SA = S >> 2;
            const int Sr = S & 3;
            const int bstart = SA + (Sr ? 1 : 0);

            accum_range(bins, r4, t4, c4, start4, SA, tid);
            if (Sr && tid == 0) {   // split mid-float4: <=4 direct REDs
                float4 r = r4[SA], t = t4[SA];
                int4 c = c4[SA];
                float d0 = r.x - t.x, d1 = r.y - t.y, d2 = r.z - t.z, d3 = r.w - t.w;
                int e = SA * 4;
                red_u64(&g_bins[(e + 0 < S ? b0 : b1) * NUM_C + c.x].v, pack1(d0 * d0));
                red_u64(&g_bins[(e + 1 < S ? b0 : b1) * NUM_C + c.y].v, pack1(d1 * d1));
                red_u64(&g_bins[(e + 2 < S ? b0 : b1) * NUM_C + c.z].v, pack1(d2 * d2));
                red_u64(&g_bins[(e + 3 < S ? b0 : b1) * NUM_C + c.w].v, pack1(d3 * d3));
            }
            flush_bins(bins, b0, tid, true);
            accum_range(bins, r4, t4, c4, bstart, end4, tid);
            flush_bins(bins, b1, tid, false);
        }

        if (last_chunk) {
            for (int i = n4 * 4 + tid; i < n; i += THREADS) {
                float d = __ldg(&reco[i]) - __ldg(&target[i]);
                red_u64(&g_bins[__ldg(&bindex[i]) * NUM_C + __ldg(&clabel[i])].v,
                        pack1(d * d));
            }
        }
    }

    // ---- completion counter; last block finalizes ----
    __threadfence();
    __syncthreads();
    __shared__ unsigned int s_is_last;
    if (tid == 0) {
        unsigned int old = atomicAdd(&g_done, 1u);
        s_is_last = (old == (unsigned int)(nblocks - 1)) ? 1u : 0u;
    }
    __syncthreads();
    if (!s_is_last) return;
    __threadfence();

    __shared__ float s_bsum[NUM_B];
    __shared__ float s_bcnt[NUM_B];
    if (tid < NUM_B) {
        s_bsum[tid] = 0.0f;
        s_bcnt[tid] = 0.0f;
    }
    __syncthreads();

    for (int sg = tid; sg < NSEG; sg += THREADS) {
        unsigned long long v = __ldcg(&g_bins[sg].v);
        g_bins[sg].v = 0ULL;  // re-zero for next launch
        unsigned int cnt = (unsigned int)(v >> G_CNT_SHIFT);
        if (cnt) {
            float sum = (float)(v & G_SUM_MASK) * INV_SCALE;
            atomicAdd(&s_bsum[sg >> 7], sum / (float)cnt);
            atomicAdd(&s_bcnt[sg >> 7], 1.0f);
        }
    }
    __syncthreads();

    if (tid < 32) {
        float bl = 0.0f, bp = 0.0f;
        float c = s_bcnt[tid];
        if (c > 0.0f) {
            bl = s_bsum[tid] / c;
            bp = 1.0f;
        }
#pragma unroll
        for (int off = 16; off > 0; off >>= 1) {
            bl += __shfl_down_sync(0xFFFFFFFFu, bl, off);
            bp += __shfl_down_sync(0xFFFFFFFFu, bp, off);
        }
        if (tid == 0) {
            out[0] = bl / bp;
            g_done = 0u;  // reset for next launch
        }
    }
}

extern "C" void kernel_launch(void* const* d_in, const int* in_sizes, int n_in,
                              void* d_out, int out_size) {
    const float* reco = (const float*)d_in[0];
    const float* target = (const float*)d_in[1];
    const int* clabel = (const int*)d_in[2];
    const int* bindex = (const int*)d_in[3];
    float* out = (float*)d_out;

    const int n = in_sizes[0];
    const int n4 = n >> 2;
    const int chunk4 = (n4 + GRID_BLOCKS - 1) / GRID_BLOCKS;

    cudaFuncSetAttribute(fused_loss_kernel,
                         cudaFuncAttributeMaxDynamicSharedMemorySize, SMEM_BYTES);

    fused_loss_kernel<<<GRID_BLOCKS, THREADS, SMEM_BYTES>>>(
        reco, target, clabel, bindex, n, n4, chunk4, GRID_BLOCKS, out);
}